// round 1
// baseline (speedup 1.0000x reference)
#include <cuda_runtime.h>

#define NT 256

// SMEM arena offsets (in floats). Peak live set: x + d1 + a1 = 16392 floats.
#define OFF_X   0       // 8192   (dead after P2)
#define OFF_D1  8192    // 4100   (dead after band3)
#define OFF_A1  12292   // 4100   (dead after level-2 analysis)
#define OFF_D2  0       // 2054   (aliases x)
#define OFF_A2  2054    // 2054   (aliases x)
#define OFF_T1  4108    // up to 4100 (aliases x/d1 head)
#define OFF_D3  8208    // 1031   (aliases d1)
#define OFF_A3  9239    // 1031   (aliases d1)
#define OFF_T2  10270   // up to 4100 (aliases d1/a1 tails)
#define ARENA   16392

__device__ __forceinline__ float mload(const float* __restrict__ s, int t, int L) {
    t = (t < 0) ? -t : t;
    t = (t >= L) ? (2 * L - 2 - t) : t;
    return s[t];
}

// Analysis level: in[L] -> lo[M], hi[M], M = L/2 + 4. Reflect pad 7, stride 2.
__device__ __forceinline__ void analysis(const float* __restrict__ in, int L,
                                         float* __restrict__ lo_out,
                                         float* __restrict__ hi_out) {
    // db4 decomposition filters
    const float L0 = -0.0105974018f, L1f =  0.0328830117f, L2f =  0.0308413818f, L3f = -0.1870348117f;
    const float L4 = -0.0279837694f, L5  =  0.6308807679f, L6  =  0.7148465706f, L7  =  0.2303778133f;
    const float H0 = -0.2303778133f, H1  =  0.7148465706f, H2  = -0.6308807679f, H3  = -0.0279837694f;
    const float H4 =  0.1870348117f, H5  =  0.0308413818f, H6  = -0.0328830117f, H7  = -0.0105974018f;

    const int M = L / 2 + 4;
    for (int m = threadIdx.x; m < M; m += NT) {
        const int base = 2 * m - 7;
        float lo, hi;
        if (base >= 0 && base + 7 < L) {
            float v0 = in[base + 0], v1 = in[base + 1], v2 = in[base + 2], v3 = in[base + 3];
            float v4 = in[base + 4], v5 = in[base + 5], v6 = in[base + 6], v7 = in[base + 7];
            lo = fmaf(L0, v0, fmaf(L1f, v1, fmaf(L2f, v2, fmaf(L3f, v3,
                 fmaf(L4, v4, fmaf(L5, v5, fmaf(L6, v6, L7 * v7)))))));
            hi = fmaf(H0, v0, fmaf(H1, v1, fmaf(H2, v2, fmaf(H3, v3,
                 fmaf(H4, v4, fmaf(H5, v5, fmaf(H6, v6, H7 * v7)))))));
        } else {
            float v0 = mload(in, base + 0, L), v1 = mload(in, base + 1, L);
            float v2 = mload(in, base + 2, L), v3 = mload(in, base + 3, L);
            float v4 = mload(in, base + 4, L), v5 = mload(in, base + 5, L);
            float v6 = mload(in, base + 6, L), v7 = mload(in, base + 7, L);
            lo = fmaf(L0, v0, fmaf(L1f, v1, fmaf(L2f, v2, fmaf(L3f, v3,
                 fmaf(L4, v4, fmaf(L5, v5, fmaf(L6, v6, L7 * v7)))))));
            hi = fmaf(H0, v0, fmaf(H1, v1, fmaf(H2, v2, fmaf(H3, v3,
                 fmaf(H4, v4, fmaf(H5, v5, fmaf(H6, v6, H7 * v7)))))));
        }
        lo_out[m] = lo;
        hi_out[m] = hi;
    }
}

// Transpose-conv stride 2 + center-crop(7): in[Lin] -> out[2*Lin-8]. Always interior.
// Pair form: out[2q]   = w7*in[q]   + w5*in[q+1] + w3*in[q+2] + w1*in[q+3]
//            out[2q+1] = w6*in[q+1] + w4*in[q+2] + w2*in[q+3] + w0*in[q+4]
template <bool HIFILT>
__device__ __forceinline__ void synth_smem(const float* __restrict__ in, int Lin,
                                           float* __restrict__ out) {
    const float w0 = HIFILT ? -0.0105974018f :  0.2303778133f;
    const float w1 = HIFILT ? -0.0328830117f :  0.7148465706f;
    const float w2 = HIFILT ?  0.0308413818f :  0.6308807679f;
    const float w3 = HIFILT ?  0.1870348117f : -0.0279837694f;
    const float w4 = HIFILT ? -0.0279837694f : -0.1870348117f;
    const float w5 = HIFILT ? -0.6308807679f :  0.0308413818f;
    const float w6 = HIFILT ?  0.7148465706f :  0.0328830117f;
    const float w7 = HIFILT ? -0.2303778133f : -0.0105974018f;
    const int Q = Lin - 4;
    for (int q = threadIdx.x; q < Q; q += NT) {
        float x0 = in[q], x1 = in[q + 1], x2 = in[q + 2], x3 = in[q + 3], x4 = in[q + 4];
        out[2 * q]     = fmaf(w7, x0, fmaf(w5, x1, fmaf(w3, x2, w1 * x3)));
        out[2 * q + 1] = fmaf(w6, x1, fmaf(w4, x2, fmaf(w2, x3, w0 * x4)));
    }
}

template <bool HIFILT>
__device__ __forceinline__ void synth_gmem(const float* __restrict__ in, int Lin,
                                           float* __restrict__ out) {
    const float w0 = HIFILT ? -0.0105974018f :  0.2303778133f;
    const float w1 = HIFILT ? -0.0328830117f :  0.7148465706f;
    const float w2 = HIFILT ?  0.0308413818f :  0.6308807679f;
    const float w3 = HIFILT ?  0.1870348117f : -0.0279837694f;
    const float w4 = HIFILT ? -0.0279837694f : -0.1870348117f;
    const float w5 = HIFILT ? -0.6308807679f :  0.0308413818f;
    const float w6 = HIFILT ?  0.7148465706f :  0.0328830117f;
    const float w7 = HIFILT ? -0.2303778133f : -0.0105974018f;
    const int Q = Lin - 4;
    float2* __restrict__ o2 = reinterpret_cast<float2*>(out);
    for (int q = threadIdx.x; q < Q; q += NT) {
        float x0 = in[q], x1 = in[q + 1], x2 = in[q + 2], x3 = in[q + 3], x4 = in[q + 4];
        float e = fmaf(w7, x0, fmaf(w5, x1, fmaf(w3, x2, w1 * x3)));
        float o = fmaf(w6, x1, fmaf(w4, x2, fmaf(w2, x3, w0 * x4)));
        o2[q] = make_float2(e, o);
    }
}

__global__ void __launch_bounds__(NT)
dwt_kernel(const float* __restrict__ x, float* __restrict__ out) {
    extern __shared__ float s[];
    const int row = blockIdx.x;                 // 0..2047 = b*128 + c
    const float* __restrict__ xr = x + (size_t)row * 8192;

    // P1: load row into smem (float4, coalesced)
    {
        float4* s4 = reinterpret_cast<float4*>(s + OFF_X);
        const float4* x4 = reinterpret_cast<const float4*>(xr);
        for (int i = threadIdx.x; i < 8192 / 4; i += NT) s4[i] = x4[i];
    }
    __syncthreads();

    // P2: level-1 analysis  x(8192) -> a1,d1 (4100)
    analysis(s + OFF_X, 8192, s + OFF_A1, s + OFF_D1);
    __syncthreads();

    // P3: band3 = convT(d1, HI) -> gmem (8192)   [x dead; d1 read-only]
    synth_gmem<true>(s + OFF_D1, 4100, out + ((size_t)3 * 2048 + row) * 8192);

    // P4: level-2 analysis  a1(4100) -> a2,d2 (2054)   [writes alias dead x only]
    analysis(s + OFF_A1, 4100, s + OFF_A2, s + OFF_D2);
    __syncthreads();                            // d1 reads & d2/a2 writes done

    // P5a: t1 = convT(d2, HI) -> 4100
    synth_smem<true>(s + OFF_D2, 2054, s + OFF_T1);
    __syncthreads();

    // P5b: band2 = convT(t1, LO) -> gmem (8192)
    synth_gmem<false>(s + OFF_T1, 4100, out + ((size_t)2 * 2048 + row) * 8192);
    // P6: level-3 analysis  a2(2054) -> a3,d3 (1031)   [disjoint from P5b reads]
    analysis(s + OFF_A2, 2054, s + OFF_A3, s + OFF_D3);
    __syncthreads();

    // P7a: t1 = convT(d3, HI) -> 2054
    synth_smem<true>(s + OFF_D3, 1031, s + OFF_T1);
    __syncthreads();
    // P7b: t2 = convT(t1, LO) -> 4100
    synth_smem<false>(s + OFF_T1, 2054, s + OFF_T2);
    __syncthreads();
    // P7c: band1 = convT(t2, LO) -> gmem (8192);  P8a: t1 = convT(a3, LO) -> 2054
    synth_gmem<false>(s + OFF_T2, 4100, out + ((size_t)1 * 2048 + row) * 8192);
    synth_smem<false>(s + OFF_A3, 1031, s + OFF_T1);
    __syncthreads();
    // P8b: t2 = convT(t1, LO) -> 4100
    synth_smem<false>(s + OFF_T1, 2054, s + OFF_T2);
    __syncthreads();
    // P8c: band0 = convT(t2, LO) -> gmem (8192)
    synth_gmem<false>(s + OFF_T2, 4100, out + (size_t)row * 8192);
}

extern "C" void kernel_launch(void* const* d_in, const int* in_sizes, int n_in,
                              void* d_out, int out_size) {
    const float* x = (const float*)d_in[0];
    float* out = (float*)d_out;
    // 65568 B dynamic smem > 48KB default: raise the limit (idempotent, capture-safe).
    cudaFuncSetAttribute(dwt_kernel, cudaFuncAttributeMaxDynamicSharedMemorySize,
                         ARENA * (int)sizeof(float));
    dwt_kernel<<<2048, NT, ARENA * sizeof(float)>>>(x, out);
}

// round 2
// speedup vs baseline: 1.1036x; 1.1036x over previous
#include <cuda_runtime.h>

#define NT 256
#define PADL 4

// SMEM arena (float offsets). All offsets multiple of 4 (16B alignment).
#define OFF_XE   0       // 4112  (4+4096+8)        dead after level-1 analysis
#define OFF_XO   4112    // 4112
#define OFF_D1   8224    // 4104                    dead after band3 synth
#define OFF_A1E  12328   // 2064  (4+2050+8)        dead after level-2 analysis
#define OFF_A1O  14392   // 2064  -> arena end 16456
#define OFF_A2E  0       // 1040  (4+1027+8)  [aliases XE]
#define OFF_A2O  1040    // 1040
#define OFF_D2   2080    // 2056
#define OFF_T1   4136    // 4104 -> 8240
#define OFF_T2   8240    // holds 2054 (aliases dead D1)
#define OFF_U    10296   // 2054 -> 12350
#define OFF_D3   12344   // 1032 (aliases dead A1E region)
#define OFF_A3   13376   // 1032 -> 14408
#define OFF_V    0       // 4100 (aliases dead A2/D2)
#define ARENA    16456

// Polyphase analysis: lo[m] = sum_j wO[j]*Xo[m-4+j] + wE[j]*Xe[m-3+j]  (wO=w[0,2,4,6], wE=w[1,3,5,7])
// xe/xo are LOGICAL base pointers (pad folded: xe[-4..] valid).
// If SPLIT: lo written even/odd-split into ae/ao (logical ptrs, pads written too); else contiguous loc.
// hi always contiguous (synth consumers need no pads).
template<bool SPLIT>
__device__ __forceinline__ void analysis_v(
    const float* __restrict__ xe, const float* __restrict__ xo, int M,
    float* __restrict__ ae, float* __restrict__ ao, int LeN,
    float* __restrict__ loc, float* __restrict__ hic)
{
    const float A0=-0.0105974018f, A1= 0.0308413818f, A2=-0.0279837694f, A3= 0.7148465706f; // DEC_LO odd phase
    const float B0= 0.0328830117f, B1=-0.1870348117f, B2= 0.6308807679f, B3= 0.2303778133f; // DEC_LO even phase
    const float C0=-0.2303778133f, C1=-0.6308807679f, C2= 0.1870348117f, C3=-0.0328830117f; // DEC_HI odd phase
    const float E0= 0.7148465706f, E1=-0.0279837694f, E2= 0.0308413818f, E3=-0.0105974018f; // DEC_HI even phase
    const int G = (M + 3) >> 2;
    for (int g = threadIdx.x; g < G; g += NT) {
        const int m0 = 4 * g;
        float4 oa = *reinterpret_cast<const float4*>(xo + 4*g - 4);
        float4 ob = *reinterpret_cast<const float4*>(xo + 4*g);
        float4 ea = *reinterpret_cast<const float4*>(xe + 4*g - 4);
        float4 eb = *reinterpret_cast<const float4*>(xe + 4*g);
        float ov[8] = {oa.x,oa.y,oa.z,oa.w,ob.x,ob.y,ob.z,ob.w};
        float ev[8] = {ea.x,ea.y,ea.z,ea.w,eb.x,eb.y,eb.z,eb.w};
        float lo[4], hi[4];
        #pragma unroll
        for (int r = 0; r < 4; r++) {
            lo[r] = fmaf(A0, ov[r], fmaf(A1, ov[r+1], fmaf(A2, ov[r+2], fmaf(A3, ov[r+3],
                    fmaf(B0, ev[r+1], fmaf(B1, ev[r+2], fmaf(B2, ev[r+3], B3*ev[r+4])))))));
            hi[r] = fmaf(C0, ov[r], fmaf(C1, ov[r+1], fmaf(C2, ov[r+2], fmaf(C3, ov[r+3],
                    fmaf(E0, ev[r+1], fmaf(E1, ev[r+2], fmaf(E2, ev[r+3], E3*ev[r+4])))))));
        }
        if (m0 + 3 < M) {
            *reinterpret_cast<float4*>(hic + m0) = make_float4(hi[0],hi[1],hi[2],hi[3]);
            if (SPLIT) {
                *reinterpret_cast<float2*>(ae + 2*g) = make_float2(lo[0], lo[2]);
                *reinterpret_cast<float2*>(ao + 2*g) = make_float2(lo[1], lo[3]);
            } else {
                *reinterpret_cast<float4*>(loc + m0) = make_float4(lo[0],lo[1],lo[2],lo[3]);
            }
        } else {
            #pragma unroll
            for (int r = 0; r < 4; r++) if (m0 + r < M) {
                hic[m0+r] = hi[r];
                if (SPLIT) { int m = m0 + r; if (m & 1) ao[m>>1] = lo[r]; else ae[m>>1] = lo[r]; }
                else loc[m0+r] = lo[r];
            }
        }
        if (SPLIT) {
            // Mirrored pads of the lo output (next level's analysis input), reflect: a[-t]=a[t], a[L-1+t]=a[L-1-t]
            #pragma unroll
            for (int r = 0; r < 4; r++) {
                const int m = m0 + r;
                if (m >= 1 && m <= 8) {
                    if (m & 1) ao[-((m+1)>>1)] = lo[r];
                    else       ae[-(m>>1)]     = lo[r];
                }
                if (m >= M-17 && m <= M-2) {
                    if (m & 1) ao[LeN + ((M-3-m)>>1)] = lo[r];
                    else       ae[LeN + ((M-2-m)>>1)] = lo[r];
                }
            }
        }
    }
}

// Transpose-conv stride2 + crop7: in[Lin] -> out[2*Lin-8], always interior.
// out[2q]   = w7*in[q]   + w5*in[q+1] + w3*in[q+2] + w1*in[q+3]
// out[2q+1] = w6*in[q+1] + w4*in[q+2] + w2*in[q+3] + w0*in[q+4]
template<bool HIF>
__device__ __forceinline__ void synth_v(const float* __restrict__ in, int Lin, float* __restrict__ out)
{
    const float w0 = HIF ? -0.0105974018f :  0.2303778133f;
    const float w1 = HIF ? -0.0328830117f :  0.7148465706f;
    const float w2 = HIF ?  0.0308413818f :  0.6308807679f;
    const float w3 = HIF ?  0.1870348117f : -0.0279837694f;
    const float w4 = HIF ? -0.0279837694f : -0.1870348117f;
    const float w5 = HIF ? -0.6308807679f :  0.0308413818f;
    const float w6 = HIF ?  0.7148465706f :  0.0328830117f;
    const float w7 = HIF ? -0.2303778133f : -0.0105974018f;
    const int Q = Lin - 4;
    const int N4 = Q >> 2;
    for (int t = threadIdx.x; t < N4; t += NT) {
        float4 a = *reinterpret_cast<const float4*>(in + 4*t);
        float4 b = *reinterpret_cast<const float4*>(in + 4*t + 4);
        float v[8] = {a.x,a.y,a.z,a.w,b.x,b.y,b.z,b.w};
        float e[4], o[4];
        #pragma unroll
        for (int j = 0; j < 4; j++) {
            e[j] = fmaf(w7, v[j],   fmaf(w5, v[j+1], fmaf(w3, v[j+2], w1*v[j+3])));
            o[j] = fmaf(w6, v[j+1], fmaf(w4, v[j+2], fmaf(w2, v[j+3], w0*v[j+4])));
        }
        *reinterpret_cast<float4*>(out + 8*t)     = make_float4(e[0],o[0],e[1],o[1]);
        *reinterpret_cast<float4*>(out + 8*t + 4) = make_float4(e[2],o[2],e[3],o[3]);
    }
    const int rem = Q & 3;
    if (threadIdx.x < rem) {
        const int q = (N4 << 2) + threadIdx.x;
        float x0=in[q], x1=in[q+1], x2=in[q+2], x3=in[q+3], x4=in[q+4];
        out[2*q]   = fmaf(w7,x0,fmaf(w5,x1,fmaf(w3,x2,w1*x3)));
        out[2*q+1] = fmaf(w6,x1,fmaf(w4,x2,fmaf(w2,x3,w0*x4)));
    }
}

__global__ void __launch_bounds__(NT)
dwt_kernel(const float* __restrict__ x, float* __restrict__ out)
{
    extern __shared__ float s[];
    const int tid = threadIdx.x;
    const int row = blockIdx.x;                  // 0..2047
    const float* __restrict__ xr = x + (size_t)row * 8192;

    float* xe  = s + OFF_XE  + PADL;  float* xo  = s + OFF_XO  + PADL;
    float* a1e = s + OFF_A1E + PADL;  float* a1o = s + OFF_A1O + PADL;
    float* a2e = s + OFF_A2E + PADL;  float* a2o = s + OFF_A2O + PADL;
    float* d1 = s + OFF_D1;  float* d2 = s + OFF_D2;  float* d3 = s + OFF_D3;
    float* a3 = s + OFF_A3;  float* t1 = s + OFF_T1;  float* t2 = s + OFF_T2;
    float* u  = s + OFF_U;   float* v  = s + OFF_V;

    // A: load + even/odd deinterleave + mirror pads (pads straight from gmem)
    {
        const float4* x4 = reinterpret_cast<const float4*>(xr);
        for (int i = tid; i < 2048; i += NT) {
            float4 w = x4[i];
            *reinterpret_cast<float2*>(xe + 2*i) = make_float2(w.x, w.z);
            *reinterpret_cast<float2*>(xo + 2*i) = make_float2(w.y, w.w);
        }
        if (tid < 4)       { int j = tid + 1;  xe[-j] = xr[2*j]; }
        else if (tid < 8)  { int j = tid - 3;  xo[-j] = xr[2*j-1]; }
        else if (tid < 16) { int j = tid - 8;  xe[4096+j] = xr[8190-2*j]; }
        else if (tid < 24) { int j = tid - 16; xo[4096+j] = xr[8189-2*j]; }
    }
    __syncthreads();

    // B: level-1 analysis: x -> a1(split,+pads), d1
    analysis_v<true>(xe, xo, 4100, a1e, a1o, 2050, nullptr, d1);
    __syncthreads();

    // C: band3 = HI-synth(d1) -> gmem   ||  level-2 analysis: a1 -> a2(split,+pads), d2
    synth_v<true>(d1, 4100, out + ((size_t)(3*2048 + row)) * 8192);
    analysis_v<true>(a1e, a1o, 2054, a2e, a2o, 1027, nullptr, d2);
    __syncthreads();

    // D: t1 = HI-synth(d2) (4100)  ||  level-3 analysis: a2 -> a3(contig), d3
    synth_v<true>(d2, 2054, t1);
    analysis_v<false>(a2e, a2o, 1031, nullptr, nullptr, 0, a3, d3);
    __syncthreads();

    // E: band2 = LO-synth(t1) -> gmem  ||  t2 = HI-synth(d3) (2054)
    synth_v<false>(t1, 4100, out + ((size_t)(2*2048 + row)) * 8192);
    synth_v<true>(d3, 1031, t2);
    __syncthreads();

    // F: t1 = LO-synth(t2) (4100)  ||  u = LO-synth(a3) (2054)
    synth_v<false>(t2, 2054, t1);
    synth_v<false>(a3, 1031, u);
    __syncthreads();

    // G: band1 = LO-synth(t1) -> gmem  ||  v = LO-synth(u) (4100)
    synth_v<false>(t1, 4100, out + ((size_t)(1*2048 + row)) * 8192);
    synth_v<false>(u, 2054, v);
    __syncthreads();

    // H: band0 = LO-synth(v) -> gmem
    synth_v<false>(v, 4100, out + (size_t)row * 8192);
}

extern "C" void kernel_launch(void* const* d_in, const int* in_sizes, int n_in,
                              void* d_out, int out_size)
{
    const float* x = (const float*)d_in[0];
    float* out = (float*)d_out;
    cudaFuncSetAttribute(dwt_kernel, cudaFuncAttributeMaxDynamicSharedMemorySize,
                         ARENA * (int)sizeof(float));
    dwt_kernel<<<2048, NT, ARENA * sizeof(float)>>>(x, out);
}

// round 5
// speedup vs baseline: 1.3265x; 1.2019x over previous
#include <cuda_runtime.h>

#define NT 256
#define PADL 4

// SMEM arena (float offsets), lifetimes verified per phase:
#define OFF_A1E  0       // 2064 = 4+2050+8(+2)   live B..C
#define OFF_A1O  2064    // 2064                  live B..C
#define OFF_D1   4128    // 4104                  live B..C
#define OFF_A2E  8232    // 1040 = 4+1027+8(+1)   live C..D
#define OFF_A2O  9272    // 1040                  live C..D
#define OFF_D2   10312   // 2056                  live C..D
#define OFF_T1   4128    // 4104 (over dead d1)   live D..E
#define OFF_A3   0       // 1032 (over dead a1)   live D..F
#define OFF_D3   1032    // 1032 (over dead a1)   live D..E
#define OFF_T2   8232    // 2056 (over dead a2)   live E..F
#define OFF_T3   2080    // 4104                  live F..G
#define OFF_U    10312   // 2056 (over dead d2)   live F..G
#define OFF_V    6184    // 4104 (over dead t1/t2) live G..H
#define ARENA    12368   // 49472 bytes -> 4 CTAs/SM

__device__ __forceinline__ float gload(const float* __restrict__ x, int t) {
    t = (t < 0) ? -t : t;
    t = (t >= 8192) ? (16382 - t) : t;
    return x[t];
}

// Level-1 analysis straight from gmem. M=4100, G=1025.
// lo[m] = sum_k DEC_LO[k]*x[2m-7+k]; v[j] = x[8g-8+j] so x[2m-7+k] = v[2r+1+k].
__device__ __forceinline__ void analysis_l1(const float* __restrict__ xr,
                                            float* __restrict__ ae, float* __restrict__ ao,
                                            float* __restrict__ hic)
{
    const float WL[8] = {-0.0105974018f, 0.0328830117f, 0.0308413818f, -0.1870348117f,
                         -0.0279837694f, 0.6308807679f, 0.7148465706f,  0.2303778133f};
    const float WH[8] = {-0.2303778133f, 0.7148465706f, -0.6308807679f, -0.0279837694f,
                          0.1870348117f, 0.0308413818f, -0.0328830117f, -0.0105974018f};
    const int M = 4100, G = 1025, LeN = 2050;
    for (int g = threadIdx.x; g < G; g += NT) {
        float v[16];
        if (g >= 1 && g <= G - 2) {
            const float4* p = reinterpret_cast<const float4*>(xr + 8 * g - 8);
            float4 q0 = p[0], q1 = p[1], q2 = p[2], q3 = p[3];
            v[0]=q0.x; v[1]=q0.y; v[2]=q0.z; v[3]=q0.w;
            v[4]=q1.x; v[5]=q1.y; v[6]=q1.z; v[7]=q1.w;
            v[8]=q2.x; v[9]=q2.y; v[10]=q2.z; v[11]=q2.w;
            v[12]=q3.x; v[13]=q3.y; v[14]=q3.z; v[15]=q3.w;
        } else {
            #pragma unroll
            for (int j = 0; j < 16; j++) v[j] = gload(xr, 8 * g - 8 + j);
        }
        float lo[4], hi[4];
        #pragma unroll
        for (int r = 0; r < 4; r++) {
            float accl = WL[0] * v[2*r+1], acch = WH[0] * v[2*r+1];
            #pragma unroll
            for (int k = 1; k < 8; k++) {
                accl = fmaf(WL[k], v[2*r+1+k], accl);
                acch = fmaf(WH[k], v[2*r+1+k], acch);
            }
            lo[r] = accl; hi[r] = acch;
        }
        *reinterpret_cast<float4*>(hic + 4 * g) = make_float4(hi[0], hi[1], hi[2], hi[3]);
        *reinterpret_cast<float2*>(ae + 2 * g) = make_float2(lo[0], lo[2]);
        *reinterpret_cast<float2*>(ao + 2 * g) = make_float2(lo[1], lo[3]);
        if (g < 3 || g > G - 6) {   // mirrored pads for next-level split input
            #pragma unroll
            for (int r = 0; r < 4; r++) {
                const int m = 4 * g + r;
                if (m >= 1 && m <= 8) {
                    if (m & 1) ao[-((m + 1) >> 1)] = lo[r];
                    else       ae[-(m >> 1)]       = lo[r];
                }
                if (m >= M - 17 && m <= M - 2) {
                    if (m & 1) ao[LeN + ((M - 3 - m) >> 1)] = lo[r];
                    else       ae[LeN + ((M - 2 - m) >> 1)] = lo[r];
                }
            }
        }
    }
}

// Split-input analysis for levels 2/3 (input in smem even/odd halves with pads).
template<bool SPLIT>
__device__ __forceinline__ void analysis_v(
    const float* __restrict__ xe, const float* __restrict__ xo, int M,
    float* __restrict__ ae, float* __restrict__ ao, int LeN,
    float* __restrict__ loc, float* __restrict__ hic)
{
    const float A0=-0.0105974018f, A1= 0.0308413818f, A2=-0.0279837694f, A3= 0.7148465706f;
    const float B0= 0.0328830117f, B1=-0.1870348117f, B2= 0.6308807679f, B3= 0.2303778133f;
    const float C0=-0.2303778133f, C1=-0.6308807679f, C2= 0.1870348117f, C3=-0.0328830117f;
    const float E0= 0.7148465706f, E1=-0.0279837694f, E2= 0.0308413818f, E3=-0.0105974018f;
    const int G = (M + 3) >> 2;
    for (int g = threadIdx.x; g < G; g += NT) {
        const int m0 = 4 * g;
        float4 oa = *reinterpret_cast<const float4*>(xo + 4*g - 4);
        float4 ob = *reinterpret_cast<const float4*>(xo + 4*g);
        float4 ea = *reinterpret_cast<const float4*>(xe + 4*g - 4);
        float4 eb = *reinterpret_cast<const float4*>(xe + 4*g);
        float ov[8] = {oa.x,oa.y,oa.z,oa.w,ob.x,ob.y,ob.z,ob.w};
        float ev[8] = {ea.x,ea.y,ea.z,ea.w,eb.x,eb.y,eb.z,eb.w};
        float lo[4], hi[4];
        #pragma unroll
        for (int r = 0; r < 4; r++) {
            lo[r] = fmaf(A0, ov[r], fmaf(A1, ov[r+1], fmaf(A2, ov[r+2], fmaf(A3, ov[r+3],
                    fmaf(B0, ev[r+1], fmaf(B1, ev[r+2], fmaf(B2, ev[r+3], B3*ev[r+4])))))));
            hi[r] = fmaf(C0, ov[r], fmaf(C1, ov[r+1], fmaf(C2, ov[r+2], fmaf(C3, ov[r+3],
                    fmaf(E0, ev[r+1], fmaf(E1, ev[r+2], fmaf(E2, ev[r+3], E3*ev[r+4])))))));
        }
        if (m0 + 3 < M) {
            *reinterpret_cast<float4*>(hic + m0) = make_float4(hi[0],hi[1],hi[2],hi[3]);
            if (SPLIT) {
                *reinterpret_cast<float2*>(ae + 2*g) = make_float2(lo[0], lo[2]);
                *reinterpret_cast<float2*>(ao + 2*g) = make_float2(lo[1], lo[3]);
            } else {
                *reinterpret_cast<float4*>(loc + m0) = make_float4(lo[0],lo[1],lo[2],lo[3]);
            }
        } else {
            #pragma unroll
            for (int r = 0; r < 4; r++) if (m0 + r < M) {
                hic[m0+r] = hi[r];
                if (SPLIT) { int m = m0 + r; if (m & 1) ao[m>>1] = lo[r]; else ae[m>>1] = lo[r]; }
                else loc[m0+r] = lo[r];
            }
        }
        if (SPLIT && (g < 3 || m0 + 3 >= M - 17)) {
            #pragma unroll
            for (int r = 0; r < 4; r++) {
                const int m = m0 + r;
                if (m >= 1 && m <= 8) {
                    if (m & 1) ao[-((m+1)>>1)] = lo[r];
                    else       ae[-(m>>1)]     = lo[r];
                }
                if (m >= M-17 && m <= M-2) {
                    if (m & 1) ao[LeN + ((M-3-m)>>1)] = lo[r];
                    else       ae[LeN + ((M-2-m)>>1)] = lo[r];
                }
            }
        }
    }
}

// Transpose-conv stride2 + crop7: in[Lin] -> out[2*Lin-8], always interior.
template<bool HIF>
__device__ __forceinline__ void synth_v(const float* __restrict__ in, int Lin, float* __restrict__ out)
{
    const float w0 = HIF ? -0.0105974018f :  0.2303778133f;
    const float w1 = HIF ? -0.0328830117f :  0.7148465706f;
    const float w2 = HIF ?  0.0308413818f :  0.6308807679f;
    const float w3 = HIF ?  0.1870348117f : -0.0279837694f;
    const float w4 = HIF ? -0.0279837694f : -0.1870348117f;
    const float w5 = HIF ? -0.6308807679f :  0.0308413818f;
    const float w6 = HIF ?  0.7148465706f :  0.0328830117f;
    const float w7 = HIF ? -0.2303778133f : -0.0105974018f;
    const int Q = Lin - 4;
    const int N4 = Q >> 2;
    for (int t = threadIdx.x; t < N4; t += NT) {
        float4 a = *reinterpret_cast<const float4*>(in + 4*t);
        float4 b = *reinterpret_cast<const float4*>(in + 4*t + 4);
        float v[8] = {a.x,a.y,a.z,a.w,b.x,b.y,b.z,b.w};
        float e[4], o[4];
        #pragma unroll
        for (int j = 0; j < 4; j++) {
            e[j] = fmaf(w7, v[j],   fmaf(w5, v[j+1], fmaf(w3, v[j+2], w1*v[j+3])));
            o[j] = fmaf(w6, v[j+1], fmaf(w4, v[j+2], fmaf(w2, v[j+3], w0*v[j+4])));
        }
        *reinterpret_cast<float4*>(out + 8*t)     = make_float4(e[0],o[0],e[1],o[1]);
        *reinterpret_cast<float4*>(out + 8*t + 4) = make_float4(e[2],o[2],e[3],o[3]);
    }
    const int rem = Q & 3;
    if (threadIdx.x < rem) {
        const int q = (N4 << 2) + threadIdx.x;
        float x0=in[q], x1=in[q+1], x2=in[q+2], x3=in[q+3], x4=in[q+4];
        out[2*q]   = fmaf(w7,x0,fmaf(w5,x1,fmaf(w3,x2,w1*x3)));
        out[2*q+1] = fmaf(w6,x1,fmaf(w4,x2,fmaf(w2,x3,w0*x4)));
    }
}

__global__ void __launch_bounds__(NT, 4)
dwt_kernel(const float* __restrict__ x, float* __restrict__ out)
{
    extern __shared__ float s[];
    const int row = blockIdx.x;                  // 0..2047
    const float* __restrict__ xr = x + (size_t)row * 8192;

    float* a1e = s + OFF_A1E + PADL;  float* a1o = s + OFF_A1O + PADL;
    float* a2e = s + OFF_A2E + PADL;  float* a2o = s + OFF_A2O + PADL;
    float* d1 = s + OFF_D1;  float* d2 = s + OFF_D2;  float* d3 = s + OFF_D3;
    float* a3 = s + OFF_A3;  float* t1 = s + OFF_T1;  float* t2 = s + OFF_T2;
    float* t3 = s + OFF_T3;  float* u  = s + OFF_U;   float* v  = s + OFF_V;

    // B: level-1 analysis straight from gmem: x -> a1(split,+pads), d1
    analysis_l1(xr, a1e, a1o, d1);
    __syncthreads();

    // C: band3 = HI-synth(d1) -> gmem  ||  level-2 analysis: a1 -> a2(split,+pads), d2
    synth_v<true>(d1, 4100, out + ((size_t)(3*2048 + row)) * 8192);
    analysis_v<true>(a1e, a1o, 2054, a2e, a2o, 1027, nullptr, d2);
    __syncthreads();

    // D: t1 = HI-synth(d2) (4100)  ||  level-3 analysis: a2 -> a3(contig), d3
    synth_v<true>(d2, 2054, t1);
    analysis_v<false>(a2e, a2o, 1031, nullptr, nullptr, 0, a3, d3);
    __syncthreads();

    // E: band2 = LO-synth(t1) -> gmem  ||  t2 = HI-synth(d3) (2054)
    synth_v<false>(t1, 4100, out + ((size_t)(2*2048 + row)) * 8192);
    synth_v<true>(d3, 1031, t2);
    __syncthreads();

    // F: t3 = LO-synth(t2) (4100)  ||  u = LO-synth(a3) (2054)
    synth_v<false>(t2, 2054, t3);
    synth_v<false>(a3, 1031, u);
    __syncthreads();

    // G: band1 = LO-synth(t3) -> gmem  ||  v = LO-synth(u) (4100)
    synth_v<false>(t3, 4100, out + ((size_t)(1*2048 + row)) * 8192);
    synth_v<false>(u, 2054, v);
    __syncthreads();

    // H: band0 = LO-synth(v) -> gmem
    synth_v<false>(v, 4100, out + (size_t)row * 8192);
}

extern "C" void kernel_launch(void* const* d_in, const int* in_sizes, int n_in,
                              void* d_out, int out_size)
{
    const float* x = (const float*)d_in[0];
    float* out = (float*)d_out;
    cudaFuncSetAttribute(dwt_kernel, cudaFuncAttributeMaxDynamicSharedMemorySize,
                         ARENA * (int)sizeof(float));
    dwt_kernel<<<2048, NT, ARENA * sizeof(float)>>>(x, out);
}